// round 10
// baseline (speedup 1.0000x reference)
#include <cuda_runtime.h>
#include <cstdint>
#include <math.h>

#define F       256   // F_IN == F_OUT
#define NPW     32    // nodes per warp (contiguous run, even)
#define WPB     4     // warps per block (pool)
#define STAGES  4     // cp.async pipeline depth (nodes in flight per warp)
#define G       8     // segments per out-block in the output GEMM
#define MAX_S   4096

// Scratch (zero at module load; restored to zero by tail kernel every run)
__device__ float g_segdenom[MAX_S];
__device__ float g_pool[MAX_S * F];
__device__ int   g_done;          // last-block-done counter (returns to 0)

// ---------------------------------------------------------------------------
// cp.async helpers
// ---------------------------------------------------------------------------
__device__ __forceinline__ void cp16(unsigned int saddr, const void* gaddr) {
    asm volatile("cp.async.cg.shared.global [%0], [%1], 16;\n"
                 :: "r"(saddr), "l"(gaddr));
}
#define CP_COMMIT()  asm volatile("cp.async.commit_group;\n" ::: "memory")
#define CP_WAIT(n)   asm volatile("cp.async.wait_group %0;\n" :: "n"(n) : "memory")

// ---------------------------------------------------------------------------
// flush register accumulators for one segment
// ---------------------------------------------------------------------------
__device__ __forceinline__ void flush_seg(int seg, int lane,
                                          float4& a0, float4& a1, float& esum)
{
    float* dst = &g_pool[(size_t)seg * F];
    atomicAdd(dst + 4*lane + 0,       a0.x);
    atomicAdd(dst + 4*lane + 1,       a0.y);
    atomicAdd(dst + 4*lane + 2,       a0.z);
    atomicAdd(dst + 4*lane + 3,       a0.w);
    atomicAdd(dst + 128 + 4*lane + 0, a1.x);
    atomicAdd(dst + 128 + 4*lane + 1, a1.y);
    atomicAdd(dst + 128 + 4*lane + 2, a1.z);
    atomicAdd(dst + 128 + 4*lane + 3, a1.w);
    if (lane == 0) atomicAdd(&g_segdenom[seg], esum);
    a0 = make_float4(0.f, 0.f, 0.f, 0.f);
    a1 = make_float4(0.f, 0.f, 0.f, 0.f);
    esum = 0.f;
}

__device__ __forceinline__ float dot8(const float4& v0, const float4& v1,
                                      const float4& w0, const float4& w1)
{
    return v0.x*w0.x + v0.y*w0.y + v0.z*w0.z + v0.w*w0.w
         + v1.x*w1.x + v1.y*w1.y + v1.z*w1.z + v1.w*w1.w;
}

__device__ __forceinline__ void acc8(float e, const float4& v0, const float4& v1,
                                     float4& a0, float4& a1, float& esum)
{
    a0.x = fmaf(e, v0.x, a0.x); a0.y = fmaf(e, v0.y, a0.y);
    a0.z = fmaf(e, v0.z, a0.z); a0.w = fmaf(e, v0.w, a0.w);
    a1.x = fmaf(e, v1.x, a1.x); a1.y = fmaf(e, v1.y, a1.y);
    a1.z = fmaf(e, v1.z, a1.z); a1.w = fmaf(e, v1.w, a1.w);
    esum += e;
}

// ---------------------------------------------------------------------------
// Kernel 1: warp-autonomous pooling with per-warp cp.async smem ring.
//   Each warp owns a 4-stage x 1KB ring; lane l stages/reads bytes
//   [16l,16l+16) and [512+16l,512+16l+16) of each node row (self-consistent,
//   no cross-lane smem visibility needed). Pairs of nodes are processed with
//   interleaved shuffle-reduce chains.
// ---------------------------------------------------------------------------
__global__ __launch_bounds__(WPB * 32, 11) void pool_kernel(
    const float* __restrict__ x, const int* __restrict__ batch,
    const float* __restrict__ W_gate, const float* __restrict__ b_gate,
    float* __restrict__ e_out, int N)
{
    __shared__ float sbuf[WPB][STAGES][F];     // 16 KB per block
    const int lane  = threadIdx.x & 31;
    const int warp  = threadIdx.x >> 5;
    const int wbase = (blockIdx.x * WPB + warp) * NPW;
    if (wbase >= N) return;
    const int wend  = min(wbase + NPW, N);
    const int M     = wend - wbase;

    // per-lane smem addresses (u32) for this warp's ring
    const unsigned int sb   = (unsigned int)__cvta_generic_to_shared(&sbuf[warp][0][0]);
    const unsigned int off0 = (unsigned int)(lane * 16);
    const unsigned int off1 = (unsigned int)(512 + lane * 16);

    const float4* wg4 = (const float4*)W_gate;
    const float4 w0 = __ldg(wg4 + lane);
    const float4 w1 = __ldg(wg4 + lane + 32);
    const float  bg = __ldg(b_gate);

    float4 a0 = make_float4(0.f, 0.f, 0.f, 0.f);
    float4 a1 = make_float4(0.f, 0.f, 0.f, 0.f);
    float  esum    = 0.f;
    int    cur_seg = batch[wbase];

    // ---- prologue: stage nodes wbase..wbase+3 (one commit group each) ----
    #pragma unroll
    for (int st = 0; st < STAGES; st++) {
        const int idx = wbase + st;
        if (idx < wend) {
            const char* g = (const char*)(x + (size_t)idx * F);
            cp16(sb + st * 1024 + off0, g + lane * 16);
            cp16(sb + st * 1024 + off1, g + 512 + lane * 16);
        }
        CP_COMMIT();
    }

    // ---- main loop: one node pair per iteration ----
    const int npairs = M >> 1;                 // M==32 normally (even)
    for (int ip = 0; ip < npairs; ip++) {
        const int idxA = wbase + 2 * ip;
        const int idxB = idxA + 1;
        const int stA  = (2 * ip)     & (STAGES - 1);
        const int stB  = (2 * ip + 1) & (STAGES - 1);

        const int sA = batch[idxA];
        const int sB = batch[idxB];

        CP_WAIT(2);                             // two oldest groups complete

        // load both nodes from smem ring into registers
        float4 vA0, vA1, vB0, vB1;
        {
            const float* pA = &sbuf[warp][stA][0];
            const float* pB = &sbuf[warp][stB][0];
            vA0 = *(const float4*)(pA + 4 * lane);
            vA1 = *(const float4*)(pA + 128 + 4 * lane);
            vB0 = *(const float4*)(pB + 4 * lane);
            vB1 = *(const float4*)(pB + 128 + 4 * lane);
        }

        // refill the two freed stages with nodes idx+4 / idx+5
        {
            const int nA = idxA + STAGES;
            if (nA < wend) {
                const char* g = (const char*)(x + (size_t)nA * F);
                cp16(sb + stA * 1024 + off0, g + lane * 16);
                cp16(sb + stA * 1024 + off1, g + 512 + lane * 16);
            }
            CP_COMMIT();
            const int nB = idxB + STAGES;
            if (nB < wend) {
                const char* g = (const char*)(x + (size_t)nB * F);
                cp16(sb + stB * 1024 + off0, g + lane * 16);
                cp16(sb + stB * 1024 + off1, g + 512 + lane * 16);
            }
            CP_COMMIT();
        }

        // two independent dot/butterfly chains
        float pA = dot8(vA0, vA1, w0, w1);
        float pB = dot8(vB0, vB1, w0, w1);
        #pragma unroll
        for (int offv = 16; offv; offv >>= 1) {
            pA += __shfl_xor_sync(0xffffffffu, pA, offv);
            pB += __shfl_xor_sync(0xffffffffu, pB, offv);
        }
        const float eA = __expf(pA + bg);
        const float eB = __expf(pB + bg);
        if (lane == 0) *(float2*)(e_out + idxA) = make_float2(eA, eB);  // idxA even

        if (sA != cur_seg) { flush_seg(cur_seg, lane, a0, a1, esum); cur_seg = sA; }
        acc8(eA, vA0, vA1, a0, a1, esum);
        if (sB != cur_seg) { flush_seg(cur_seg, lane, a0, a1, esum); cur_seg = sB; }
        acc8(eB, vB0, vB1, a0, a1, esum);
    }

    // ---- odd remainder node (direct from gmem) ----
    if (M & 1) {
        const int idx = wend - 1;
        const float4* r = (const float4*)(x + (size_t)idx * F);
        const float4 q0 = __ldcs(r + lane);
        const float4 q1 = __ldcs(r + lane + 32);
        const int s = batch[idx];
        float p = dot8(q0, q1, w0, w1);
        #pragma unroll
        for (int offv = 16; offv; offv >>= 1) p += __shfl_xor_sync(0xffffffffu, p, offv);
        const float e = __expf(p + bg);
        if (lane == 0) e_out[idx] = e;
        if (s != cur_seg) { flush_seg(cur_seg, lane, a0, a1, esum); cur_seg = s; }
        acc8(e, q0, q1, a0, a1, esum);
    }

    CP_WAIT(0);                                 // drain before exit
    flush_seg(cur_seg, lane, a0, a1, esum);
}

// ---------------------------------------------------------------------------
// Kernel 2 (fused tail), 1024-thread blocks:
//   blocks [0, n_out):   out-GEMM with 4-way k-split; zeroes g_pool.
//   blocks [n_out, ...): per-node gate normalize (coalesced).
//   g_segdenom zeroed by the LAST block to finish (fence+barrier+counter).
// ---------------------------------------------------------------------------
__global__ __launch_bounds__(1024) void tail_kernel(
    const int* __restrict__ batch, float* __restrict__ gate_io,
    const float* __restrict__ W_nn, const float* __restrict__ b_nn,
    float* __restrict__ out, int N, int S, int n_out_blocks, int n_total_blocks)
{
    if ((int)blockIdx.x < n_out_blocks) {
        const int tid = threadIdx.x;
        const int f   = tid & 255;
        const int kq  = tid >> 8;            // 0..3
        const int s0  = blockIdx.x * G;
        __shared__ float p_sh[G][F];         // pool/denom          (8 KB)
        __shared__ float partial[3][G][F];   // kq=1..3 partials   (24 KB)

        for (int j = tid; j < G * F; j += 1024) {
            const int g  = j >> 8;
            const int ff = j & 255;
            const int s  = s0 + g;
            float v = 0.f;
            if (s < S) {
                v = g_pool[(size_t)s * F + ff] / (g_segdenom[s] + 1e-16f);
                g_pool[(size_t)s * F + ff] = 0.f;   // self-clean (sole reader)
            }
            p_sh[g][ff] = v;
        }
        __syncthreads();

        float acc[G];
        #pragma unroll
        for (int g = 0; g < G; g++) acc[g] = 0.f;

        const int k0 = kq * 64;
        #pragma unroll 8
        for (int k = k0; k < k0 + 64; k++) {
            const float w = __ldg(&W_nn[(size_t)k * F + f]);
            #pragma unroll
            for (int g = 0; g < G; g++) acc[g] = fmaf(p_sh[g][k], w, acc[g]);
        }

        if (kq > 0) {
            #pragma unroll
            for (int g = 0; g < G; g++) partial[kq - 1][g][f] = acc[g];
        }
        __syncthreads();

        if (kq == 0) {
            const float bn = __ldg(&b_nn[f]);
            #pragma unroll
            for (int g = 0; g < G; g++) {
                const int s = s0 + g;
                if (s < S) {
                    float t = acc[g] + partial[0][g][f] + partial[1][g][f] + partial[2][g][f];
                    const float d    = g_segdenom[s];
                    const float gsum = d / (d + 1e-16f);    // ~1 nonempty, 0 empty
                    out[(size_t)s * F + f] = t + gsum * bn;
                }
            }
        }
    } else {
        const int n = (blockIdx.x - n_out_blocks) * 1024 + threadIdx.x;
        if (n < N) gate_io[n] = gate_io[n] / (g_segdenom[batch[n]] + 1e-16f);
    }

    // ---- last-done block zeroes g_segdenom and resets the counter ----
    __shared__ int last_sh;
    __threadfence();                 // order my reads/writes globally
    __syncthreads();                 // ALL warps of this block done reading
    if (threadIdx.x == 0) {
        const int v = atomicAdd(&g_done, 1);
        last_sh = (v == n_total_blocks - 1);
    }
    __syncthreads();
    if (last_sh) {
        for (int i = threadIdx.x; i < S; i += 1024) g_segdenom[i] = 0.f;
        if (threadIdx.x == 0) g_done = 0;   // state restored for next replay
    }
}

// ---------------------------------------------------------------------------
// kernel_launch: identify inputs by element counts
//   inputs (dict order): x, batch, [size], W_gate, b_gate, W_nn, b_nn
//   output layout: [out (S*F floats)] then [gate (N floats)]
// ---------------------------------------------------------------------------
extern "C" void kernel_launch(void* const* d_in, const int* in_sizes, int n_in,
                              void* d_out, int out_size)
{
    int xi = 0;
    for (int i = 1; i < n_in; i++) if (in_sizes[i] > in_sizes[xi]) xi = i;
    const float* x = (const float*)d_in[xi];
    const int N = in_sizes[xi] / F;

    const int*   batch  = nullptr;
    const float* W_gate = nullptr;
    const float* b_gate = nullptr;
    const float* W_nn   = nullptr;
    const float* b_nn   = nullptr;

    int n256 = 0;
    for (int i = 0; i < n_in; i++) {
        if (i == xi) continue;
        const int sz = in_sizes[i];
        if (sz == N)            batch = (const int*)d_in[i];
        else if (sz == F * F)   W_nn  = (const float*)d_in[i];
        else if (sz == F) {
            if (n256 == 0) W_gate = (const float*)d_in[i];   // W_gate precedes b_nn
            else           b_nn   = (const float*)d_in[i];
            n256++;
        }
        else if (sz == 1)       b_gate = (const float*)d_in[i];
    }

    const int S = (out_size - N) / F;

    float* out      = (float*)d_out;
    float* gate_out = out + (size_t)S * F;

    const int nwarps        = (N + NPW - 1) / NPW;
    const int n_out_blocks  = (S + G - 1) / G;
    const int n_gate_blocks = (N + 1023) / 1024;
    const int n_total       = n_out_blocks + n_gate_blocks;

    pool_kernel<<<(nwarps + WPB - 1) / WPB, WPB * 32>>>(x, batch, W_gate, b_gate, gate_out, N);
    tail_kernel<<<n_total, 1024>>>(batch, gate_out, W_nn, b_nn,
                                   out, N, S, n_out_blocks, n_total);
}

// round 13
// speedup vs baseline: 1.4671x; 1.4671x over previous
#include <cuda_runtime.h>
#include <cstdint>
#include <math.h>

#define F      256    // F_IN == F_OUT
#define NPW    32     // nodes per warp (contiguous run)
#define WPB    4      // warps per block (pool)
#define G      8      // segments per out-block in the output GEMM
#define MAX_S  4096

// Scratch (zero at module load; restored to zero by tail kernel every run)
__device__ float g_segdenom[MAX_S];
__device__ float g_pool[MAX_S * F];
__device__ int   g_done;          // last-block-done counter (returns to 0)

// ---------------------------------------------------------------------------
// flush register accumulators for one segment
// ---------------------------------------------------------------------------
__device__ __forceinline__ void flush_seg(int seg, int lane,
                                          float4& a0, float4& a1, float& esum)
{
    float* dst = &g_pool[(size_t)seg * F];
    atomicAdd(dst + 4*lane + 0,       a0.x);
    atomicAdd(dst + 4*lane + 1,       a0.y);
    atomicAdd(dst + 4*lane + 2,       a0.z);
    atomicAdd(dst + 4*lane + 3,       a0.w);
    atomicAdd(dst + 128 + 4*lane + 0, a1.x);
    atomicAdd(dst + 128 + 4*lane + 1, a1.y);
    atomicAdd(dst + 128 + 4*lane + 2, a1.z);
    atomicAdd(dst + 128 + 4*lane + 3, a1.w);
    if (lane == 0) atomicAdd(&g_segdenom[seg], esum);
    a0 = make_float4(0.f, 0.f, 0.f, 0.f);
    a1 = make_float4(0.f, 0.f, 0.f, 0.f);
    esum = 0.f;
}

__device__ __forceinline__ float dot8(const float4& v0, const float4& v1,
                                      const float4& w0, const float4& w1)
{
    return v0.x*w0.x + v0.y*w0.y + v0.z*w0.z + v0.w*w0.w
         + v1.x*w1.x + v1.y*w1.y + v1.z*w1.z + v1.w*w1.w;
}

__device__ __forceinline__ void acc8(float e, const float4& v0, const float4& v1,
                                     float4& a0, float4& a1, float& esum)
{
    a0.x = fmaf(e, v0.x, a0.x); a0.y = fmaf(e, v0.y, a0.y);
    a0.z = fmaf(e, v0.z, a0.z); a0.w = fmaf(e, v0.w, a0.w);
    a1.x = fmaf(e, v1.x, a1.x); a1.y = fmaf(e, v1.y, a1.y);
    a1.z = fmaf(e, v1.z, a1.z); a1.w = fmaf(e, v1.w, a1.w);
    esum += e;
}

// ---------------------------------------------------------------------------
// Kernel 1: warp-autonomous pooling; QUADS of nodes with 4 interleaved
// shuffle-reduce chains + one-quad-ahead register prefetch; streaming loads.
// (R6-proven structure; batch[] read inline to trim registers.)
// ---------------------------------------------------------------------------
__global__ __launch_bounds__(WPB * 32) void pool_kernel(
    const float* __restrict__ x, const int* __restrict__ batch,
    const float* __restrict__ W_gate, const float* __restrict__ b_gate,
    float* __restrict__ e_out, int N)
{
    const int lane  = threadIdx.x & 31;
    const int warp  = threadIdx.x >> 5;
    const int wbase = (blockIdx.x * WPB + warp) * NPW;
    if (wbase >= N) return;
    const int wend      = min(wbase + NPW, N);
    const int wend_full = wbase + ((wend - wbase) & ~3);   // quad-aligned portion

    const float4* wg4 = (const float4*)W_gate;
    const float4 w0 = __ldg(wg4 + lane);
    const float4 w1 = __ldg(wg4 + lane + 32);
    const float  bg = __ldg(b_gate);

    float4 a0 = make_float4(0.f, 0.f, 0.f, 0.f);
    float4 a1 = make_float4(0.f, 0.f, 0.f, 0.f);
    float  esum    = 0.f;
    int    cur_seg = batch[wbase];

    float4 v0[4], v1[4];

    // ---- preload quad 0 ----
    #pragma unroll
    for (int k = 0; k < 4; k++) {
        const int idx = wbase + k;
        if (idx < wend) {
            const float4* r = (const float4*)(x + (size_t)idx * F);
            v0[k] = __ldcs(r + lane);
            v1[k] = __ldcs(r + lane + 32);
        }
    }

    for (int i = wbase; i < wend_full; i += 4) {
        // ---- prefetch quad i+4 ----
        float4 u0[4], u1[4];
        #pragma unroll
        for (int k = 0; k < 4; k++) {
            const int idx = i + 4 + k;
            if (idx < wend) {
                const float4* r = (const float4*)(x + (size_t)idx * F);
                u0[k] = __ldcs(r + lane);
                u1[k] = __ldcs(r + lane + 32);
            }
        }

        // ---- 4 independent dots + interleaved butterflies ----
        float p[4];
        #pragma unroll
        for (int k = 0; k < 4; k++) p[k] = dot8(v0[k], v1[k], w0, w1);
        #pragma unroll
        for (int off = 16; off; off >>= 1) {
            #pragma unroll
            for (int k = 0; k < 4; k++) p[k] += __shfl_xor_sync(0xffffffffu, p[k], off);
        }
        float e[4];
        #pragma unroll
        for (int k = 0; k < 4; k++) e[k] = __expf(p[k] + bg);

        if (lane == 0)   // i is 4-aligned, e_out 16B-aligned
            *(float4*)(e_out + i) = make_float4(e[0], e[1], e[2], e[3]);

        // ---- accumulate with boundary checks (batch read inline, L1-hot) ----
        #pragma unroll
        for (int k = 0; k < 4; k++) {
            const int s = batch[i + k];
            if (s != cur_seg) { flush_seg(cur_seg, lane, a0, a1, esum); cur_seg = s; }
            acc8(e[k], v0[k], v1[k], a0, a1, esum);
        }

        #pragma unroll
        for (int k = 0; k < 4; k++) { v0[k] = u0[k]; v1[k] = u1[k]; }
    }

    // ---- scalar epilogue for non-quad remainder ----
    for (int idx = wend_full; idx < wend; idx++) {
        const float4* r = (const float4*)(x + (size_t)idx * F);
        const float4 q0 = __ldcs(r + lane);
        const float4 q1 = __ldcs(r + lane + 32);
        const int s = batch[idx];
        float p = dot8(q0, q1, w0, w1);
        #pragma unroll
        for (int off = 16; off; off >>= 1) p += __shfl_xor_sync(0xffffffffu, p, off);
        const float e = __expf(p + bg);
        if (lane == 0) e_out[idx] = e;
        if (s != cur_seg) { flush_seg(cur_seg, lane, a0, a1, esum); cur_seg = s; }
        acc8(e, q0, q1, a0, a1, esum);
    }

    flush_seg(cur_seg, lane, a0, a1, esum);
}

// ---------------------------------------------------------------------------
// Kernel 2 (fused tail), 1024-thread blocks:
//   blocks [0, n_out):   out-GEMM with 4-way k-split (f = tid&255,
//                        kq = tid>>8); partials combined in smem; zeroes
//                        g_pool (sole reader).
//   blocks [n_out, ...): per-node gate normalize (coalesced).
//   g_segdenom zeroed by the LAST block to finish (fence+barrier+counter).
// ---------------------------------------------------------------------------
__global__ __launch_bounds__(1024) void tail_kernel(
    const int* __restrict__ batch, float* __restrict__ gate_io,
    const float* __restrict__ W_nn, const float* __restrict__ b_nn,
    float* __restrict__ out, int N, int S, int n_out_blocks, int n_total_blocks)
{
    if ((int)blockIdx.x < n_out_blocks) {
        const int tid = threadIdx.x;
        const int f   = tid & 255;
        const int kq  = tid >> 8;            // 0..3
        const int s0  = blockIdx.x * G;
        __shared__ float p_sh[G][F];         // pool/denom          (8 KB)
        __shared__ float partial[3][G][F];   // kq=1..3 partials   (24 KB)

        for (int j = tid; j < G * F; j += 1024) {
            const int g  = j >> 8;
            const int ff = j & 255;
            const int s  = s0 + g;
            float v = 0.f;
            if (s < S) {
                v = g_pool[(size_t)s * F + ff] / (g_segdenom[s] + 1e-16f);
                g_pool[(size_t)s * F + ff] = 0.f;   // self-clean (sole reader)
            }
            p_sh[g][ff] = v;
        }
        __syncthreads();

        float acc[G];
        #pragma unroll
        for (int g = 0; g < G; g++) acc[g] = 0.f;

        const int k0 = kq * 64;
        #pragma unroll 8
        for (int k = k0; k < k0 + 64; k++) {
            const float w = __ldg(&W_nn[(size_t)k * F + f]);
            #pragma unroll
            for (int g = 0; g < G; g++) acc[g] = fmaf(p_sh[g][k], w, acc[g]);
        }

        if (kq > 0) {
            #pragma unroll
            for (int g = 0; g < G; g++) partial[kq - 1][g][f] = acc[g];
        }
        __syncthreads();

        if (kq == 0) {
            const float bn = __ldg(&b_nn[f]);
            #pragma unroll
            for (int g = 0; g < G; g++) {
                const int s = s0 + g;
                if (s < S) {
                    float t = acc[g] + partial[0][g][f] + partial[1][g][f] + partial[2][g][f];
                    const float d    = g_segdenom[s];
                    const float gsum = d / (d + 1e-16f);    // ~1 nonempty, 0 empty
                    out[(size_t)s * F + f] = t + gsum * bn;
                }
            }
        }
    } else {
        const int n = (blockIdx.x - n_out_blocks) * 1024 + threadIdx.x;
        if (n < N) gate_io[n] = gate_io[n] / (g_segdenom[batch[n]] + 1e-16f);
    }

    // ---- last-done block zeroes g_segdenom and resets the counter ----
    __shared__ int last_sh;
    __threadfence();                 // order my reads/writes globally
    __syncthreads();                 // ALL warps of this block done reading
    if (threadIdx.x == 0) {
        const int v = atomicAdd(&g_done, 1);
        last_sh = (v == n_total_blocks - 1);
    }
    __syncthreads();
    if (last_sh) {
        for (int i = threadIdx.x; i < S; i += 1024) g_segdenom[i] = 0.f;
        if (threadIdx.x == 0) g_done = 0;   // state restored for next replay
    }
}

// ---------------------------------------------------------------------------
// kernel_launch: identify inputs by element counts
//   inputs (dict order): x, batch, [size], W_gate, b_gate, W_nn, b_nn
//   output layout: [out (S*F floats)] then [gate (N floats)]
// ---------------------------------------------------------------------------
extern "C" void kernel_launch(void* const* d_in, const int* in_sizes, int n_in,
                              void* d_out, int out_size)
{
    int xi = 0;
    for (int i = 1; i < n_in; i++) if (in_sizes[i] > in_sizes[xi]) xi = i;
    const float* x = (const float*)d_in[xi];
    const int N = in_sizes[xi] / F;

    const int*   batch  = nullptr;
    const float* W_gate = nullptr;
    const float* b_gate = nullptr;
    const float* W_nn   = nullptr;
    const float* b_nn   = nullptr;

    int n256 = 0;
    for (int i = 0; i < n_in; i++) {
        if (i == xi) continue;
        const int sz = in_sizes[i];
        if (sz == N)            batch = (const int*)d_in[i];
        else if (sz == F * F)   W_nn  = (const float*)d_in[i];
        else if (sz == F) {
            if (n256 == 0) W_gate = (const float*)d_in[i];   // W_gate precedes b_nn
            else           b_nn   = (const float*)d_in[i];
            n256++;
        }
        else if (sz == 1)       b_gate = (const float*)d_in[i];
    }

    const int S = (out_size - N) / F;

    float* out      = (float*)d_out;
    float* gate_out = out + (size_t)S * F;

    const int nwarps        = (N + NPW - 1) / NPW;
    const int n_out_blocks  = (S + G - 1) / G;
    const int n_gate_blocks = (N + 1023) / 1024;
    const int n_total       = n_out_blocks + n_gate_blocks;

    pool_kernel<<<(nwarps + WPB - 1) / WPB, WPB * 32>>>(x, batch, W_gate, b_gate, gate_out, N);
    tail_kernel<<<n_total, 1024>>>(batch, gate_out, W_nn, b_nn,
                                   out, N, S, n_out_blocks, n_total);
}